// round 12
// baseline (speedup 1.0000x reference)
#include <cuda_runtime.h>
#include <cuda_fp16.h>
#include <cstdint>

// ---------------------------------------------------------------------------
// Fused LSTM cell (R12): persistent-CTA GEMM.
//   1) prep: activations -> g_Af16 [Bx1024] f16; W -> g_Wf16 [2048x1024] f16
//      transposed + gate-interleave permuted.
//   2) lstm_gemm: PERSISTENT kernel, grid = 2*SMs. Each CTA loops over tiles
//      (128 rows x 128 preact cols). The cp.async 3-stage K64 mbarrier
//      pipeline runs CONTINUOUSLY across tiles (global chunk counter), so
//      pipeline fill is paid once per CTA, and each tile's epilogue overlaps
//      the next tile's loads. 8 warps (2Mx4N), 2 CTAs/SM, mma.m16n8k16.f16.
// ---------------------------------------------------------------------------

__device__ static __align__(16) uint16_t g_Af16[16384ull * 1024ull];
__device__ static __align__(16) uint16_t g_Wf16[2048ull * 1024ull];

static constexpr int NST      = 3;
static constexpr int STAGE    = 32768;              // A 16KB + B 16KB
static constexpr int MBAR_OFF = NST * STAGE;        // 98304: full[3], empty[3]
static constexpr int SMEM     = MBAR_OFF + 64;      // 98368

__device__ __forceinline__ uint32_t s2u(const void* p) {
    uint32_t a;
    asm("{ .reg .u64 t; cvta.to.shared.u64 t, %1; cvt.u32.u64 %0, t; }"
        : "=r"(a) : "l"(p));
    return a;
}
__device__ __forceinline__ void mbar_init(uint32_t mb, uint32_t cnt) {
    asm volatile("mbarrier.init.shared.b64 [%0], %1;" :: "r"(mb), "r"(cnt)
                 : "memory");
}
__device__ __forceinline__ void mbar_arrive(uint32_t mb) {
    asm volatile("mbarrier.arrive.shared.b64 _, [%0];" :: "r"(mb) : "memory");
}
__device__ __forceinline__ void cp_arrive_noinc(uint32_t mb) {
    asm volatile("cp.async.mbarrier.arrive.noinc.shared.b64 [%0];" :: "r"(mb)
                 : "memory");
}
__device__ __forceinline__ void mbar_wait(uint32_t mb, uint32_t parity) {
    asm volatile(
        "{\n\t.reg .pred P;\n\t"
        "WL_%=:\n\t"
        "mbarrier.try_wait.parity.acquire.cta.shared::cta.b64 P, [%0], %1, 0x989680;\n\t"
        "@P bra WD_%=;\n\t"
        "bra WL_%=;\n\t"
        "WD_%=:\n\t}"
        :: "r"(mb), "r"(parity) : "memory");
}
__device__ __forceinline__ void ldsm4(uint32_t& r0, uint32_t& r1,
                                      uint32_t& r2, uint32_t& r3, uint32_t a) {
    asm volatile("ldmatrix.sync.aligned.m8n8.x4.shared.b16 {%0,%1,%2,%3}, [%4];"
                 : "=r"(r0), "=r"(r1), "=r"(r2), "=r"(r3) : "r"(a));
}
__device__ __forceinline__ void mma_f16(float* d, const uint32_t* a,
                                        uint32_t b0, uint32_t b1) {
    asm volatile(
        "mma.sync.aligned.m16n8k16.row.col.f32.f16.f16.f32 "
        "{%0,%1,%2,%3}, {%4,%5,%6,%7}, {%8,%9}, {%0,%1,%2,%3};\n"
        : "+f"(d[0]), "+f"(d[1]), "+f"(d[2]), "+f"(d[3])
        : "r"(a[0]), "r"(a[1]), "r"(a[2]), "r"(a[3]), "r"(b0), "r"(b1));
}
__device__ __forceinline__ float tanh_a(float x) {
    float y;
    asm("tanh.approx.f32 %0, %1;" : "=f"(y) : "f"(x));
    return y;
}
__device__ __forceinline__ float sigm_a(float x) {
    return fmaf(tanh_a(0.5f * x), 0.5f, 0.5f);
}

// ---- prepass: activations + weights -> f16 scratch -------------------------
__global__ __launch_bounds__(256)
void prep(const float* __restrict__ x, const float* __restrict__ h,
          const float* __restrict__ s, const float* __restrict__ t,
          const float* __restrict__ Wx, const float* __restrict__ Wh,
          const float* __restrict__ Ws, const float* __restrict__ Wt,
          int ablocks) {
    const int tid = threadIdx.x;
    if ((int)blockIdx.x < ablocks) {
        const int idx = blockIdx.x * 256 + tid;
        const int r   = idx >> 6;
        const int k16 = (idx & 63) * 16;
        const float* ap; int astr, kl;
        if (k16 < 256)      { ap = x; astr = 256; kl = k16;       }
        else if (k16 < 768) { ap = h; astr = 512; kl = k16 - 256; }
        else if (k16 < 896) { ap = s; astr = 128; kl = k16 - 768; }
        else                { ap = t; astr = 128; kl = k16 - 896; }
        const float4* src = reinterpret_cast<const float4*>(
            ap + (size_t)r * astr + kl);
        const float4 f0 = src[0], f1 = src[1], f2 = src[2], f3 = src[3];
        __half2 h0 = __floats2half2_rn(f0.x, f0.y);
        __half2 h1 = __floats2half2_rn(f0.z, f0.w);
        __half2 h2 = __floats2half2_rn(f1.x, f1.y);
        __half2 h3 = __floats2half2_rn(f1.z, f1.w);
        __half2 h4 = __floats2half2_rn(f2.x, f2.y);
        __half2 h5 = __floats2half2_rn(f2.z, f2.w);
        __half2 h6 = __floats2half2_rn(f3.x, f3.y);
        __half2 h7 = __floats2half2_rn(f3.z, f3.w);
        uint4* dst = reinterpret_cast<uint4*>(g_Af16 + (size_t)r * 1024 + k16);
        dst[0] = make_uint4(*(uint32_t*)&h0, *(uint32_t*)&h1,
                            *(uint32_t*)&h2, *(uint32_t*)&h3);
        dst[1] = make_uint4(*(uint32_t*)&h4, *(uint32_t*)&h5,
                            *(uint32_t*)&h6, *(uint32_t*)&h7);
    } else {
        __shared__ float tile[32][33];
        const int wb = blockIdx.x - ablocks;      // 0..2047
        const int k0 = (wb & 31) * 32;
        const int r0 = (wb >> 5) * 32;
        const float* wp; int kl;
        if (k0 < 256)      { wp = Wx; kl = k0;       }
        else if (k0 < 768) { wp = Wh; kl = k0 - 256; }
        else if (k0 < 896) { wp = Ws; kl = k0 - 768; }
        else               { wp = Wt; kl = k0 - 896; }
        const int tx = tid & 31, ty = tid >> 5;
        const int r = r0 + tx;
        const int c = ((r >> 3) & 3) * 512 + (r >> 7) * 32 +
                      ((r >> 5) & 3) * 8 + (r & 7);
#pragma unroll
        for (int i = 0; i < 4; i++) {
            const int ky = ty + 8 * i;
            tile[tx][ky] = wp[(size_t)(kl + ky) * 2048 + c];
        }
        __syncthreads();
#pragma unroll
        for (int i = 0; i < 4; i++) {
            const int ky = ty + 8 * i;
            g_Wf16[(size_t)(r0 + ky) * 1024 + k0 + tx] =
                __half_as_ushort(__float2half_rn(tile[ky][tx]));
        }
    }
}

// ---- persistent GEMM + gates ------------------------------------------------
__global__ __launch_bounds__(256, 2)
void lstm_gemm(const float* __restrict__ cin, const float* __restrict__ bh,
               float* __restrict__ out, int B, int TX, int NT)
{
    extern __shared__ __align__(1024) char smem[];
    const uint32_t sb = s2u(smem);
    const uint32_t mb_full  = sb + MBAR_OFF;        // 3 x 8B, count 256
    const uint32_t mb_empty = sb + MBAR_OFF + 24;   // 3 x 8B, count 8 (warps)
    const int tid  = threadIdx.x;
    const int wid  = tid >> 5;
    const int lane = tid & 31;
    const int gid  = lane >> 2;
    const int tig  = lane & 3;
    const int wm   = wid & 1;       // M half  (64 rows)
    const int wn   = wid >> 1;      // N quarter (32 preact cols)
    const int cta  = blockIdx.x;
    const int G    = gridDim.x;

    if (tid == 0) {
#pragma unroll
        for (int i = 0; i < NST; i++) {
            mbar_init(mb_full + 8 * i, 256);
            mbar_init(mb_empty + 8 * i, 8);
        }
    }
    __syncthreads();

    // ---- producer: running chunk counter pn ----------------------------
    int pn = 0;
    auto try_issue = [&]() {
        const int tt = cta + (pn >> 4) * G;    // tile of chunk pn
        if (tt >= NT) return;
        const int st  = pn % 3;
        const int lap = pn / 3;
        if (pn >= 3)
            mbar_wait(mb_empty + 8 * st, (lap - 1) & 1);
        const uint16_t* Ab = g_Af16 + (size_t)(tt % TX) * 128 * 1024;
        const uint16_t* Wb = g_Wf16 + (size_t)(tt / TX) * 128 * 1024;
        const int kg = (pn & 15) * 64;
        const uint32_t base = sb + st * STAGE;
#pragma unroll
        for (int i = 0; i < 8; i++) {
            const int v   = tid + i * 256;
            const int mat = v >> 10;
            const int row = (v >> 3) & 127;
            const int seg = v & 7;
            const uint32_t dst = base + mat * 16384 + row * 128 +
                                 (seg ^ (row & 7)) * 16;
            const uint16_t* src = (mat ? Wb : Ab) +
                                  (size_t)row * 1024 + kg + seg * 8;
            asm volatile("cp.async.cg.shared.global [%0], [%1], 16;"
                         :: "r"(dst), "l"(src));
        }
        cp_arrive_noinc(mb_full + 8 * st);
        pn++;
    };

    float acc[4][4][4];
    auto compute_ks = [&](int st, int ks) {
        const uint32_t ab = sb + st * STAGE;
        const uint32_t bb = ab + 16384;
        uint32_t a[4][4];
#pragma unroll
        for (int mt = 0; mt < 4; mt++) {
            const int row = wm * 64 + mt * 16 + (lane & 7) +
                            8 * ((lane >> 3) & 1);
            const int seg = 2 * ks + ((lane >> 4) & 1);
            const uint32_t addr = ab + row * 128 + (seg ^ (row & 7)) * 16;
            ldsm4(a[mt][0], a[mt][1], a[mt][2], a[mt][3], addr);
        }
        uint32_t b[4][2];
#pragma unroll
        for (int np = 0; np < 2; np++) {
            const int row = wn * 32 + np * 16 + (lane & 7) +
                            8 * ((lane >> 4) & 1);
            const int seg = 2 * ks + ((lane >> 3) & 1);
            const uint32_t addr = bb + row * 128 + (seg ^ (row & 7)) * 16;
            ldsm4(b[2 * np][0], b[2 * np][1],
                  b[2 * np + 1][0], b[2 * np + 1][1], addr);
        }
#pragma unroll
        for (int mt = 0; mt < 4; mt++)
#pragma unroll
            for (int nt = 0; nt < 4; nt++)
                mma_f16(acc[mt][nt], a[mt], b[nt][0], b[nt][1]);
    };

    try_issue();
    try_issue();

    // ---- persistent tile loop -------------------------------------------
    int cn = 0;
#pragma unroll 1
    for (int tt = cta; tt < NT; tt += G) {
#pragma unroll
        for (int mt = 0; mt < 4; mt++)
#pragma unroll
            for (int nt = 0; nt < 4; nt++)
#pragma unroll
                for (int q = 0; q < 4; q++) acc[mt][nt][q] = 0.0f;

#pragma unroll 1
        for (int s = 0; s < 16; s++) {
            const int st  = cn % 3;
            const int lap = cn / 3;
            mbar_wait(mb_full + 8 * st, lap & 1);
            compute_ks(st, 0);
            try_issue();
            compute_ks(st, 1);
            compute_ks(st, 2);
            compute_ks(st, 3);
            if (lane == 0)
                mbar_arrive(mb_empty + 8 * st);
            cn++;
        }

        // ---- epilogue for tile tt (overlaps next tile's loads) ----------
        const int m0  = (tt % TX) * 128;
        const int by  = tt / TX;
        const int jl0 = wn * 8 + 2 * tig;
        const int jg  = by * 32 + jl0;
        float bv[4][2];
#pragma unroll
        for (int g = 0; g < 4; g++) {
            bv[g][0] = __ldg(&bh[g * 512 + jg]);
            bv[g][1] = __ldg(&bh[g * 512 + jg + 1]);
        }
        const int rowbase = m0 + wm * 64 + gid;
#pragma unroll
        for (int mt = 0; mt < 4; mt++) {
#pragma unroll
            for (int rh = 0; rh < 2; rh++) {
                const int row = rowbase + mt * 16 + 8 * rh;
                const float2 cv = *reinterpret_cast<const float2*>(
                    cin + (size_t)row * 512 + jg);
                float hn[2], cn2[2];
#pragma unroll
                for (int e = 0; e < 2; e++) {
                    const int ci = rh * 2 + e;
                    const float pi = acc[mt][0][ci] + bv[0][e];
                    const float pf = acc[mt][1][ci] + bv[1][e];
                    const float po = acc[mt][2][ci] + bv[2][e];
                    const float pc = acc[mt][3][ci] + bv[3][e];
                    const float ig = sigm_a(pi);
                    const float fg = sigm_a(pf);
                    const float og = sigm_a(po);
                    const float cg = tanh_a(pc);
                    const float c_ = (e ? cv.y : cv.x);
                    cn2[e] = fg * c_ + ig * cg;
                    hn[e]  = tanh_a(og * cn2[e]);
                }
                *reinterpret_cast<float2*>(out + (size_t)row * 512 + jg) =
                    make_float2(hn[0], hn[1]);
                *reinterpret_cast<float2*>(out + (size_t)B * 512 +
                                           (size_t)row * 512 + jg) =
                    make_float2(cn2[0], cn2[1]);
            }
        }
    }
}

extern "C" void kernel_launch(void* const* d_in, const int* in_sizes, int n_in,
                              void* d_out, int out_size) {
    const float* x  = (const float*)d_in[0];
    const float* h  = (const float*)d_in[1];
    const float* c  = (const float*)d_in[2];
    const float* sp = (const float*)d_in[3];
    const float* tp = (const float*)d_in[4];
    const float* Wx = (const float*)d_in[5];
    const float* Wh = (const float*)d_in[6];
    const float* bh = (const float*)d_in[7];
    const float* Ws = (const float*)d_in[8];
    const float* Wt = (const float*)d_in[9];
    float* out = (float*)d_out;

    const int B = in_sizes[0] / 256;   // x is [B, 256]
    const int ablocks = (B * 1024) / (256 * 16);

    static int gsize = 0;
    if (!gsize) {
        int sm = 0;
        cudaDeviceGetAttribute(&sm, cudaDevAttrMultiProcessorCount, 0);
        gsize = sm * 2;
        cudaFuncSetAttribute(lstm_gemm,
                             cudaFuncAttributeMaxDynamicSharedMemorySize, SMEM);
    }
    const int TX = B / 128;
    const int NT = TX * 16;
    const int grid = (gsize < NT) ? gsize : NT;

    prep<<<ablocks + 2048, 256>>>(x, h, sp, tp, Wx, Wh, Ws, Wt, ablocks);
    lstm_gemm<<<grid, 256, SMEM>>>(c, bh, out, B, TX, NT);
}

// round 13
// speedup vs baseline: 1.0274x; 1.0274x over previous
#include <cuda_runtime.h>
#include <cuda_fp16.h>
#include <cstdint>

// ---------------------------------------------------------------------------
// Fused LSTM cell (R13): wide-N CTA to cut L2 bytes/MAC.
//   1) prep: activations -> g_Af16 [Bx1024] f16; W -> g_Wf16 [2048x1024] f16
//      transposed + gate-interleave permuted (unchanged from R11).
//   2) lstm_gemm: CTA tile 128 rows x 256 preact cols (A re-read 8x instead
//      of 16x -> 22.9 B/KMAC, was 31.2). 512 threads = 16 warps (2M x 8N),
//      warp tile 64x32 (same per-warp structure as R11). cp.async 3-stage
//      K64 mbarrier pipeline, ldmatrix + mma.m16n8k16.f16, 1 CTA/SM.
// ---------------------------------------------------------------------------

__device__ static __align__(16) uint16_t g_Af16[16384ull * 1024ull];
__device__ static __align__(16) uint16_t g_Wf16[2048ull * 1024ull];

static constexpr int NST      = 3;
static constexpr int A_BYTES  = 128 * 128;          // 16 KB
static constexpr int B_BYTES  = 256 * 128;          // 32 KB
static constexpr int STAGE    = A_BYTES + B_BYTES;  // 48 KB
static constexpr int MBAR_OFF = NST * STAGE;        // 147456
static constexpr int SMEM     = MBAR_OFF + 64;

__device__ __forceinline__ uint32_t s2u(const void* p) {
    uint32_t a;
    asm("{ .reg .u64 t; cvta.to.shared.u64 t, %1; cvt.u32.u64 %0, t; }"
        : "=r"(a) : "l"(p));
    return a;
}
__device__ __forceinline__ void mbar_init(uint32_t mb, uint32_t cnt) {
    asm volatile("mbarrier.init.shared.b64 [%0], %1;" :: "r"(mb), "r"(cnt)
                 : "memory");
}
__device__ __forceinline__ void mbar_arrive(uint32_t mb) {
    asm volatile("mbarrier.arrive.shared.b64 _, [%0];" :: "r"(mb) : "memory");
}
__device__ __forceinline__ void cp_arrive_noinc(uint32_t mb) {
    asm volatile("cp.async.mbarrier.arrive.noinc.shared.b64 [%0];" :: "r"(mb)
                 : "memory");
}
__device__ __forceinline__ void mbar_wait(uint32_t mb, uint32_t parity) {
    asm volatile(
        "{\n\t.reg .pred P;\n\t"
        "WL_%=:\n\t"
        "mbarrier.try_wait.parity.acquire.cta.shared::cta.b64 P, [%0], %1, 0x989680;\n\t"
        "@P bra WD_%=;\n\t"
        "bra WL_%=;\n\t"
        "WD_%=:\n\t}"
        :: "r"(mb), "r"(parity) : "memory");
}
__device__ __forceinline__ void ldsm4(uint32_t& r0, uint32_t& r1,
                                      uint32_t& r2, uint32_t& r3, uint32_t a) {
    asm volatile("ldmatrix.sync.aligned.m8n8.x4.shared.b16 {%0,%1,%2,%3}, [%4];"
                 : "=r"(r0), "=r"(r1), "=r"(r2), "=r"(r3) : "r"(a));
}
__device__ __forceinline__ void mma_f16(float* d, const uint32_t* a,
                                        uint32_t b0, uint32_t b1) {
    asm volatile(
        "mma.sync.aligned.m16n8k16.row.col.f32.f16.f16.f32 "
        "{%0,%1,%2,%3}, {%4,%5,%6,%7}, {%8,%9}, {%0,%1,%2,%3};\n"
        : "+f"(d[0]), "+f"(d[1]), "+f"(d[2]), "+f"(d[3])
        : "r"(a[0]), "r"(a[1]), "r"(a[2]), "r"(a[3]), "r"(b0), "r"(b1));
}
__device__ __forceinline__ float tanh_a(float x) {
    float y;
    asm("tanh.approx.f32 %0, %1;" : "=f"(y) : "f"(x));
    return y;
}
__device__ __forceinline__ float sigm_a(float x) {
    return fmaf(tanh_a(0.5f * x), 0.5f, 0.5f);
}

// ---- prepass: activations + weights -> f16 scratch -------------------------
__global__ __launch_bounds__(256)
void prep(const float* __restrict__ x, const float* __restrict__ h,
          const float* __restrict__ s, const float* __restrict__ t,
          const float* __restrict__ Wx, const float* __restrict__ Wh,
          const float* __restrict__ Ws, const float* __restrict__ Wt,
          int ablocks) {
    const int tid = threadIdx.x;
    if ((int)blockIdx.x < ablocks) {
        const int idx = blockIdx.x * 256 + tid;
        const int r   = idx >> 6;
        const int k16 = (idx & 63) * 16;
        const float* ap; int astr, kl;
        if (k16 < 256)      { ap = x; astr = 256; kl = k16;       }
        else if (k16 < 768) { ap = h; astr = 512; kl = k16 - 256; }
        else if (k16 < 896) { ap = s; astr = 128; kl = k16 - 768; }
        else                { ap = t; astr = 128; kl = k16 - 896; }
        const float4* src = reinterpret_cast<const float4*>(
            ap + (size_t)r * astr + kl);
        const float4 f0 = src[0], f1 = src[1], f2 = src[2], f3 = src[3];
        __half2 h0 = __floats2half2_rn(f0.x, f0.y);
        __half2 h1 = __floats2half2_rn(f0.z, f0.w);
        __half2 h2 = __floats2half2_rn(f1.x, f1.y);
        __half2 h3 = __floats2half2_rn(f1.z, f1.w);
        __half2 h4 = __floats2half2_rn(f2.x, f2.y);
        __half2 h5 = __floats2half2_rn(f2.z, f2.w);
        __half2 h6 = __floats2half2_rn(f3.x, f3.y);
        __half2 h7 = __floats2half2_rn(f3.z, f3.w);
        uint4* dst = reinterpret_cast<uint4*>(g_Af16 + (size_t)r * 1024 + k16);
        dst[0] = make_uint4(*(uint32_t*)&h0, *(uint32_t*)&h1,
                            *(uint32_t*)&h2, *(uint32_t*)&h3);
        dst[1] = make_uint4(*(uint32_t*)&h4, *(uint32_t*)&h5,
                            *(uint32_t*)&h6, *(uint32_t*)&h7);
    } else {
        __shared__ float tile[32][33];
        const int wb = blockIdx.x - ablocks;      // 0..2047
        const int k0 = (wb & 31) * 32;
        const int r0 = (wb >> 5) * 32;
        const float* wp; int kl;
        if (k0 < 256)      { wp = Wx; kl = k0;       }
        else if (k0 < 768) { wp = Wh; kl = k0 - 256; }
        else if (k0 < 896) { wp = Ws; kl = k0 - 768; }
        else               { wp = Wt; kl = k0 - 896; }
        const int tx = tid & 31, ty = tid >> 5;
        const int r = r0 + tx;
        const int c = ((r >> 3) & 3) * 512 + (r >> 7) * 32 +
                      ((r >> 5) & 3) * 8 + (r & 7);
#pragma unroll
        for (int i = 0; i < 4; i++) {
            const int ky = ty + 8 * i;
            tile[tx][ky] = wp[(size_t)(kl + ky) * 2048 + c];
        }
        __syncthreads();
#pragma unroll
        for (int i = 0; i < 4; i++) {
            const int ky = ty + 8 * i;
            g_Wf16[(size_t)(r0 + ky) * 1024 + k0 + tx] =
                __half_as_ushort(__float2half_rn(tile[ky][tx]));
        }
    }
}

// ---- main GEMM + gates ------------------------------------------------------
__global__ __launch_bounds__(512, 1)
void lstm_gemm(const float* __restrict__ cin, const float* __restrict__ bh,
               float* __restrict__ out, int B)
{
    extern __shared__ __align__(1024) char smem[];
    const uint32_t sb = s2u(smem);
    const uint32_t mb_full  = sb + MBAR_OFF;        // 3 x 8B, count 512
    const uint32_t mb_empty = sb + MBAR_OFF + 24;   // 3 x 8B, count 16 (warps)
    const int tid  = threadIdx.x;
    const int wid  = tid >> 5;
    const int lane = tid & 31;
    const int gid  = lane >> 2;
    const int tig  = lane & 3;
    const int wm   = wid & 1;       // M half  (64 rows)
    const int wn   = wid >> 1;      // 0..7 : 32 preact cols each
    const int m0   = blockIdx.x * 128;
    const int by   = blockIdx.y;    // 256-preact-col block (64 hidden cols)

    float acc[4][4][4];
#pragma unroll
    for (int mt = 0; mt < 4; mt++)
#pragma unroll
        for (int nt = 0; nt < 4; nt++)
#pragma unroll
            for (int q = 0; q < 4; q++) acc[mt][nt][q] = 0.0f;

    const uint16_t* Abase = g_Af16 + (size_t)m0 * 1024;
    const uint16_t* Wbase = g_Wf16 + (size_t)by * 256 * 1024;

    // issue chunk q into stage stq; cp.async completion -> full[stq] arrival
    // tasks: 3072 x 16B (A: 1024, B: 2048), 6 per thread
    auto issue = [&](int q, int stq) {
        const uint32_t base = sb + stq * STAGE;
        const int kg = q * 64;
#pragma unroll
        for (int i = 0; i < 6; i++) {
            const int v = tid + i * 512;
            uint32_t dst;
            const uint16_t* src;
            if (v < 1024) {            // A: 128 rows x 8 segs
                const int row = v >> 3, seg = v & 7;
                dst = base + row * 128 + ((seg ^ (row & 7)) * 16);
                src = Abase + (size_t)row * 1024 + kg + seg * 8;
            } else {                   // B: 256 rows x 8 segs
                const int u = v - 1024;
                const int row = u >> 3, seg = u & 7;
                dst = base + A_BYTES + row * 128 + ((seg ^ (row & 7)) * 16);
                src = Wbase + (size_t)row * 1024 + kg + seg * 8;
            }
            asm volatile("cp.async.cg.shared.global [%0], [%1], 16;"
                         :: "r"(dst), "l"(src));
        }
        cp_arrive_noinc(mb_full + 8 * stq);
    };

    // one k16 step of the chunk in stage st
    auto compute_ks = [&](int st, int ks) {
        const uint32_t ab = sb + st * STAGE;
        const uint32_t bb = ab + A_BYTES;
        uint32_t a[4][4];
#pragma unroll
        for (int mt = 0; mt < 4; mt++) {
            const int row = wm * 64 + mt * 16 + (lane & 7) +
                            8 * ((lane >> 3) & 1);
            const int seg = 2 * ks + ((lane >> 4) & 1);
            const uint32_t addr = ab + row * 128 + (seg ^ (row & 7)) * 16;
            ldsm4(a[mt][0], a[mt][1], a[mt][2], a[mt][3], addr);
        }
        uint32_t b[4][2];
#pragma unroll
        for (int np = 0; np < 2; np++) {
            const int row = wn * 32 + np * 16 + (lane & 7) +
                            8 * ((lane >> 4) & 1);
            const int seg = 2 * ks + ((lane >> 3) & 1);
            const uint32_t addr = bb + row * 128 + (seg ^ (row & 7)) * 16;
            ldsm4(b[2 * np][0], b[2 * np][1],
                  b[2 * np + 1][0], b[2 * np + 1][1], addr);
        }
#pragma unroll
        for (int mt = 0; mt < 4; mt++)
#pragma unroll
            for (int nt = 0; nt < 4; nt++)
                mma_f16(acc[mt][nt], a[mt], b[nt][0], b[nt][1]);
    };

    // prologue: mbarrier init, 2 stages in flight
    if (tid == 0) {
#pragma unroll
        for (int i = 0; i < NST; i++) {
            mbar_init(mb_full + 8 * i, 512);
            mbar_init(mb_empty + 8 * i, 16);
        }
    }
    __syncthreads();
    issue(0, 0);
    issue(1, 1);

    // mainloop
#pragma unroll 1
    for (int s = 0; s < 16; s++) {
        const int d  = (s * 11) >> 5;        // s / 3 for s < 18
        const int st = s - 3 * d;
        mbar_wait(mb_full + 8 * st, d & 1);
        compute_ks(st, 0);
        const int q = s + 2;
        if (q < 16) {
            const int dq  = (q * 11) >> 5;
            const int stq = q - 3 * dq;
            if (q >= NST)
                mbar_wait(mb_empty + 8 * stq, (dq - 1) & 1);
            issue(q, stq);
        }
        compute_ks(st, 1);
        compute_ks(st, 2);
        compute_ks(st, 3);
        if (lane == 0)
            mbar_arrive(mb_empty + 8 * st);
    }

    // epilogue: register-local gates, per-warp retirement
    // warp wn owns g_Wf16 rows [by*256 + wn*32, +32):
    //   jb = by*2 + (wn>>2), within-32 col = (wn&3)*8 + 2*tig + e, gate = nt
    const int jb  = by * 2 + (wn >> 2);
    const int jl0 = (wn & 3) * 8 + 2 * tig;
    const int jg  = jb * 32 + jl0;
    float bv[4][2];
#pragma unroll
    for (int g = 0; g < 4; g++) {
        bv[g][0] = __ldg(&bh[g * 512 + jg]);
        bv[g][1] = __ldg(&bh[g * 512 + jg + 1]);
    }
    const int rowbase = m0 + wm * 64 + gid;
#pragma unroll
    for (int mt = 0; mt < 4; mt++) {
#pragma unroll
        for (int rh = 0; rh < 2; rh++) {
            const int row = rowbase + mt * 16 + 8 * rh;
            const float2 cv = *reinterpret_cast<const float2*>(
                cin + (size_t)row * 512 + jg);
            float hn[2], cn[2];
#pragma unroll
            for (int e = 0; e < 2; e++) {
                const int ci = rh * 2 + e;
                const float pi = acc[mt][0][ci] + bv[0][e];
                const float pf = acc[mt][1][ci] + bv[1][e];
                const float po = acc[mt][2][ci] + bv[2][e];
                const float pc = acc[mt][3][ci] + bv[3][e];
                const float ig = sigm_a(pi);
                const float fg = sigm_a(pf);
                const float og = sigm_a(po);
                const float cg = tanh_a(pc);
                const float c_ = (e ? cv.y : cv.x);
                cn[e] = fg * c_ + ig * cg;
                hn[e] = tanh_a(og * cn[e]);
            }
            *reinterpret_cast<float2*>(out + (size_t)row * 512 + jg) =
                make_float2(hn[0], hn[1]);
            *reinterpret_cast<float2*>(out + (size_t)B * 512 +
                                       (size_t)row * 512 + jg) =
                make_float2(cn[0], cn[1]);
        }
    }
}

extern "C" void kernel_launch(void* const* d_in, const int* in_sizes, int n_in,
                              void* d_out, int out_size) {
    const float* x  = (const float*)d_in[0];
    const float* h  = (const float*)d_in[1];
    const float* c  = (const float*)d_in[2];
    const float* sp = (const float*)d_in[3];
    const float* tp = (const float*)d_in[4];
    const float* Wx = (const float*)d_in[5];
    const float* Wh = (const float*)d_in[6];
    const float* bh = (const float*)d_in[7];
    const float* Ws = (const float*)d_in[8];
    const float* Wt = (const float*)d_in[9];
    float* out = (float*)d_out;

    const int B = in_sizes[0] / 256;   // x is [B, 256]
    const int ablocks = (B * 1024) / (256 * 16);

    static int smem_set = 0;
    if (!smem_set) {
        cudaFuncSetAttribute(lstm_gemm,
                             cudaFuncAttributeMaxDynamicSharedMemorySize, SMEM);
        smem_set = 1;
    }

    prep<<<ablocks + 2048, 256>>>(x, h, sp, tp, Wx, Wh, Ws, Wt, ablocks);
    lstm_gemm<<<dim3(B / 128, 8), 512, SMEM>>>(c, bh, out, B);
}

// round 14
// speedup vs baseline: 1.0817x; 1.0528x over previous
#include <cuda_runtime.h>
#include <cuda_fp16.h>
#include <cstdint>

// ---------------------------------------------------------------------------
// Fused LSTM cell (R14): 64x64 warp tiles to cut smem-port traffic.
//   1) prep: activations -> g_Af16 [Bx1024] f16; W -> g_Wf16 [2048x1024] f16
//      transposed, permutation for 2 N-warps x (fh,gate) interleave:
//      row r -> orig col ((r>>3)&3)*512 + (r>>7)*32 + ((r>>6)&1)*16
//               + ((r>>5)&1)*8 + (r&7)
//   2) lstm_gemm: CTA 128x128, 4 warps (2M x 2N), warp tile 64x64
//      (acc 128 f32 regs; 2 CTAs/SM within the 64K-reg file).
//      LDSM redundancy: A x2 (was x4), B x2 -> smem traffic -25%.
//      cp.async 3-stage K64 mbarrier pipeline, mma.m16n8k16.f16.
// ---------------------------------------------------------------------------

__device__ static __align__(16) uint16_t g_Af16[16384ull * 1024ull];
__device__ static __align__(16) uint16_t g_Wf16[2048ull * 1024ull];

static constexpr int NST      = 3;
static constexpr int STAGE    = 32768;              // A 16KB + B 16KB
static constexpr int MBAR_OFF = NST * STAGE;        // 98304
static constexpr int SMEM     = MBAR_OFF + 64;      // 98368

__device__ __forceinline__ uint32_t s2u(const void* p) {
    uint32_t a;
    asm("{ .reg .u64 t; cvta.to.shared.u64 t, %1; cvt.u32.u64 %0, t; }"
        : "=r"(a) : "l"(p));
    return a;
}
__device__ __forceinline__ void mbar_init(uint32_t mb, uint32_t cnt) {
    asm volatile("mbarrier.init.shared.b64 [%0], %1;" :: "r"(mb), "r"(cnt)
                 : "memory");
}
__device__ __forceinline__ void mbar_arrive(uint32_t mb) {
    asm volatile("mbarrier.arrive.shared.b64 _, [%0];" :: "r"(mb) : "memory");
}
__device__ __forceinline__ void cp_arrive_noinc(uint32_t mb) {
    asm volatile("cp.async.mbarrier.arrive.noinc.shared.b64 [%0];" :: "r"(mb)
                 : "memory");
}
__device__ __forceinline__ void mbar_wait(uint32_t mb, uint32_t parity) {
    asm volatile(
        "{\n\t.reg .pred P;\n\t"
        "WL_%=:\n\t"
        "mbarrier.try_wait.parity.acquire.cta.shared::cta.b64 P, [%0], %1, 0x989680;\n\t"
        "@P bra WD_%=;\n\t"
        "bra WL_%=;\n\t"
        "WD_%=:\n\t}"
        :: "r"(mb), "r"(parity) : "memory");
}
__device__ __forceinline__ void ldsm4(uint32_t& r0, uint32_t& r1,
                                      uint32_t& r2, uint32_t& r3, uint32_t a) {
    asm volatile("ldmatrix.sync.aligned.m8n8.x4.shared.b16 {%0,%1,%2,%3}, [%4];"
                 : "=r"(r0), "=r"(r1), "=r"(r2), "=r"(r3) : "r"(a));
}
__device__ __forceinline__ void mma_f16(float* d, const uint32_t* a,
                                        uint32_t b0, uint32_t b1) {
    asm volatile(
        "mma.sync.aligned.m16n8k16.row.col.f32.f16.f16.f32 "
        "{%0,%1,%2,%3}, {%4,%5,%6,%7}, {%8,%9}, {%0,%1,%2,%3};\n"
        : "+f"(d[0]), "+f"(d[1]), "+f"(d[2]), "+f"(d[3])
        : "r"(a[0]), "r"(a[1]), "r"(a[2]), "r"(a[3]), "r"(b0), "r"(b1));
}
__device__ __forceinline__ float tanh_a(float x) {
    float y;
    asm("tanh.approx.f32 %0, %1;" : "=f"(y) : "f"(x));
    return y;
}
__device__ __forceinline__ float sigm_a(float x) {
    return fmaf(tanh_a(0.5f * x), 0.5f, 0.5f);
}

// ---- prepass: activations + weights -> f16 scratch -------------------------
__global__ __launch_bounds__(256)
void prep(const float* __restrict__ x, const float* __restrict__ h,
          const float* __restrict__ s, const float* __restrict__ t,
          const float* __restrict__ Wx, const float* __restrict__ Wh,
          const float* __restrict__ Ws, const float* __restrict__ Wt,
          int ablocks) {
    const int tid = threadIdx.x;
    if ((int)blockIdx.x < ablocks) {
        const int idx = blockIdx.x * 256 + tid;
        const int r   = idx >> 6;
        const int k16 = (idx & 63) * 16;
        const float* ap; int astr, kl;
        if (k16 < 256)      { ap = x; astr = 256; kl = k16;       }
        else if (k16 < 768) { ap = h; astr = 512; kl = k16 - 256; }
        else if (k16 < 896) { ap = s; astr = 128; kl = k16 - 768; }
        else                { ap = t; astr = 128; kl = k16 - 896; }
        const float4* src = reinterpret_cast<const float4*>(
            ap + (size_t)r * astr + kl);
        const float4 f0 = src[0], f1 = src[1], f2 = src[2], f3 = src[3];
        __half2 h0 = __floats2half2_rn(f0.x, f0.y);
        __half2 h1 = __floats2half2_rn(f0.z, f0.w);
        __half2 h2 = __floats2half2_rn(f1.x, f1.y);
        __half2 h3 = __floats2half2_rn(f1.z, f1.w);
        __half2 h4 = __floats2half2_rn(f2.x, f2.y);
        __half2 h5 = __floats2half2_rn(f2.z, f2.w);
        __half2 h6 = __floats2half2_rn(f3.x, f3.y);
        __half2 h7 = __floats2half2_rn(f3.z, f3.w);
        uint4* dst = reinterpret_cast<uint4*>(g_Af16 + (size_t)r * 1024 + k16);
        dst[0] = make_uint4(*(uint32_t*)&h0, *(uint32_t*)&h1,
                            *(uint32_t*)&h2, *(uint32_t*)&h3);
        dst[1] = make_uint4(*(uint32_t*)&h4, *(uint32_t*)&h5,
                            *(uint32_t*)&h6, *(uint32_t*)&h7);
    } else {
        __shared__ float tile[32][33];
        const int wb = blockIdx.x - ablocks;      // 0..2047
        const int k0 = (wb & 31) * 32;
        const int r0 = (wb >> 5) * 32;
        const float* wp; int kl;
        if (k0 < 256)      { wp = Wx; kl = k0;       }
        else if (k0 < 768) { wp = Wh; kl = k0 - 256; }
        else if (k0 < 896) { wp = Ws; kl = k0 - 768; }
        else               { wp = Wt; kl = k0 - 896; }
        const int tx = tid & 31, ty = tid >> 5;
        const int r = r0 + tx;
        // R14 permutation: wn = (r>>6)&1 (16-col), fh = (r>>5)&1 (8-col)
        const int c = ((r >> 3) & 3) * 512 + (r >> 7) * 32 +
                      ((r >> 6) & 1) * 16 + ((r >> 5) & 1) * 8 + (r & 7);
#pragma unroll
        for (int i = 0; i < 4; i++) {
            const int ky = ty + 8 * i;
            tile[tx][ky] = wp[(size_t)(kl + ky) * 2048 + c];
        }
        __syncthreads();
#pragma unroll
        for (int i = 0; i < 4; i++) {
            const int ky = ty + 8 * i;
            g_Wf16[(size_t)(r0 + ky) * 1024 + k0 + tx] =
                __half_as_ushort(__float2half_rn(tile[ky][tx]));
        }
    }
}

// ---- main GEMM + gates ------------------------------------------------------
__global__ __launch_bounds__(128, 2)
void lstm_gemm(const float* __restrict__ cin, const float* __restrict__ bh,
               float* __restrict__ out, int B)
{
    extern __shared__ __align__(1024) char smem[];
    const uint32_t sb = s2u(smem);
    const uint32_t mb_full  = sb + MBAR_OFF;        // 3 x 8B, count 128
    const uint32_t mb_empty = sb + MBAR_OFF + 24;   // 3 x 8B, count 4 (warps)
    const int tid  = threadIdx.x;
    const int wid  = tid >> 5;
    const int lane = tid & 31;
    const int gid  = lane >> 2;
    const int tig  = lane & 3;
    const int wm   = wid >> 1;      // M half  (64 rows)
    const int wn   = wid & 1;       // N half  (64 preact cols)
    const int m0   = blockIdx.x * 128;
    const int by   = blockIdx.y;    // 32-hidden-col block

    float acc[4][8][4];             // [mt][f][c], f = fh*4 + gate
#pragma unroll
    for (int mt = 0; mt < 4; mt++)
#pragma unroll
        for (int f = 0; f < 8; f++)
#pragma unroll
            for (int q = 0; q < 4; q++) acc[mt][f][q] = 0.0f;

    const uint16_t* Abase = g_Af16 + (size_t)m0 * 1024;
    const uint16_t* Wbase = g_Wf16 + (size_t)by * 128 * 1024;

    // issue chunk q into stage stq: 2048 x 16B tasks, 16 per thread
    auto issue = [&](int q, int stq) {
        const uint32_t base = sb + stq * STAGE;
        const int kg = q * 64;
#pragma unroll
        for (int i = 0; i < 16; i++) {
            const int v   = tid + i * 128;
            const int mat = v >> 10;
            const int row = (v >> 3) & 127;
            const int seg = v & 7;
            const uint32_t dst = base + mat * 16384 + row * 128 +
                                 ((seg ^ (row & 7)) * 16);
            const uint16_t* src = (mat ? Wbase : Abase) +
                                  (size_t)row * 1024 + kg + seg * 8;
            asm volatile("cp.async.cg.shared.global [%0], [%1], 16;"
                         :: "r"(dst), "l"(src));
        }
        cp_arrive_noinc(mb_full + 8 * stq);
    };

    // one k16 step of the chunk in stage st
    auto compute_ks = [&](int st, int ks) {
        const uint32_t ab = sb + st * STAGE;
        const uint32_t bb = ab + 16384;
        uint32_t a[4][4];
#pragma unroll
        for (int mt = 0; mt < 4; mt++) {
            const int row = wm * 64 + mt * 16 + (lane & 7) +
                            8 * ((lane >> 3) & 1);
            const int seg = 2 * ks + ((lane >> 4) & 1);
            const uint32_t addr = ab + row * 128 + (seg ^ (row & 7)) * 16;
            ldsm4(a[mt][0], a[mt][1], a[mt][2], a[mt][3], addr);
        }
        uint32_t b[8][2];
#pragma unroll
        for (int np = 0; np < 4; np++) {
            const int row = wn * 64 + np * 16 + (lane & 7) +
                            8 * ((lane >> 4) & 1);
            const int seg = 2 * ks + ((lane >> 3) & 1);
            const uint32_t addr = bb + row * 128 + (seg ^ (row & 7)) * 16;
            ldsm4(b[2 * np][0], b[2 * np][1],
                  b[2 * np + 1][0], b[2 * np + 1][1], addr);
        }
#pragma unroll
        for (int mt = 0; mt < 4; mt++)
#pragma unroll
            for (int f = 0; f < 8; f++)
                mma_f16(acc[mt][f], a[mt], b[f][0], b[f][1]);
    };

    // prologue: mbarrier init, 2 stages in flight
    if (tid == 0) {
#pragma unroll
        for (int i = 0; i < NST; i++) {
            mbar_init(mb_full + 8 * i, 128);
            mbar_init(mb_empty + 8 * i, 4);
        }
    }
    __syncthreads();
    issue(0, 0);
    issue(1, 1);

    // mainloop
#pragma unroll 1
    for (int s = 0; s < 16; s++) {
        const int d  = (s * 11) >> 5;        // s / 3 for s < 18
        const int st = s - 3 * d;
        mbar_wait(mb_full + 8 * st, d & 1);
        compute_ks(st, 0);
        const int q = s + 2;
        if (q < 16) {
            const int dq  = (q * 11) >> 5;
            const int stq = q - 3 * dq;
            if (q >= NST)
                mbar_wait(mb_empty + 8 * stq, (dq - 1) & 1);
            issue(q, stq);
        }
        compute_ks(st, 1);
        compute_ks(st, 2);
        compute_ks(st, 3);
        if (lane == 0)
            mbar_arrive(mb_empty + 8 * st);
    }

    // epilogue: register-local gates, per-warp retirement
    // warp covers preact cols wn*64 + (fh*4+gate)*8 + v
    // hidden col jg = by*32 + wn*16 + fh*8 + 2*tig (+e)
    const int rowbase = m0 + wm * 64 + gid;
#pragma unroll
    for (int fh = 0; fh < 2; fh++) {
        const int jg = by * 32 + wn * 16 + fh * 8 + 2 * tig;
        float bv[4][2];
#pragma unroll
        for (int g = 0; g < 4; g++) {
            bv[g][0] = __ldg(&bh[g * 512 + jg]);
            bv[g][1] = __ldg(&bh[g * 512 + jg + 1]);
        }
#pragma unroll
        for (int mt = 0; mt < 4; mt++) {
#pragma unroll
            for (int rh = 0; rh < 2; rh++) {
                const int row = rowbase + mt * 16 + 8 * rh;
                const float2 cv = *reinterpret_cast<const float2*>(
                    cin + (size_t)row * 512 + jg);
                float hn[2], cn[2];
#pragma unroll
                for (int e = 0; e < 2; e++) {
                    const int ci = rh * 2 + e;
                    const float pi = acc[mt][fh * 4 + 0][ci] + bv[0][e];
                    const float pf = acc[mt][fh * 4 + 1][ci] + bv[1][e];
                    const float po = acc[mt][fh * 4 + 2][ci] + bv[2][e];
                    const float pc = acc[mt][fh * 4 + 3][ci] + bv[3][e];
                    const float ig = sigm_a(pi);
                    const float fg = sigm_a(pf);
                    const float og = sigm_a(po);
                    const float cg = tanh_a(pc);
                    const float c_ = (e ? cv.y : cv.x);
                    cn[e] = fg * c_ + ig * cg;
                    hn[e] = tanh_a(og * cn[e]);
                }
                *reinterpret_cast<float2*>(out + (size_t)row * 512 + jg) =
                    make_float2(hn[0], hn[1]);
                *reinterpret_cast<float2*>(out + (size_t)B * 512 +
                                           (size_t)row * 512 + jg) =
                    make_float2(cn[0], cn[1]);
            }
        }
    }
}

extern "C" void kernel_launch(void* const* d_in, const int* in_sizes, int n_in,
                              void* d_out, int out_size) {
    const float* x  = (const float*)d_in[0];
    const float* h  = (const float*)d_in[1];
    const float* c  = (const float*)d_in[2];
    const float* sp = (const float*)d_in[3];
    const float* tp = (const float*)d_in[4];
    const float* Wx = (const float*)d_in[5];
    const float* Wh = (const float*)d_in[6];
    const float* bh = (const float*)d_in[7];
    const float* Ws = (const float*)d_in[8];
    const float* Wt = (const float*)d_in[9];
    float* out = (float*)d_out;

    const int B = in_sizes[0] / 256;   // x is [B, 256]
    const int ablocks = (B * 1024) / (256 * 16);

    static int smem_set = 0;
    if (!smem_set) {
        cudaFuncSetAttribute(lstm_gemm,
                             cudaFuncAttributeMaxDynamicSharedMemorySize, SMEM);
        smem_set = 1;
    }

    prep<<<ablocks + 2048, 256>>>(x, h, sp, tp, Wx, Wh, Ws, Wt, ablocks);
    lstm_gemm<<<dim3(B / 128, 16), 128, SMEM>>>(c, bh, out, B);
}

// round 15
// speedup vs baseline: 1.0942x; 1.0116x over previous
#include <cuda_runtime.h>
#include <cuda_fp16.h>
#include <cstdint>

// ---------------------------------------------------------------------------
// Fused LSTM cell (R15): R11 (best known) + CTA decorrelation.
//   1) prep: activations -> g_Af16 [Bx1024] f16; W -> g_Wf16 [2048x1024] f16
//      transposed + gate-interleave permuted.
//   2) lstm_gemm: cp.async 3-stage K64 mbarrier pipeline, ldmatrix +
//      mma.m16n8k16.f16, CTA 128x128, 8 warps (2Mx4N), 2 CTAs/SM.
// R15 vs R11 (everything else frozen):
//   - per-CTA k-chunk ROTATION (kg = ((q+off)&15)*64) -> decorrelates the
//     chip-wide synchronized 9.5MB fetch bursts at chunk boundaries
//   - odd-bx CTAs nanosleep ~600ns once before first issue -> the two
//     co-resident CTAs' barrier flips interleave, covering each other's
//     wake + LDSM-ramp bubbles with MMA work
// ---------------------------------------------------------------------------

__device__ static __align__(16) uint16_t g_Af16[16384ull * 1024ull];
__device__ static __align__(16) uint16_t g_Wf16[2048ull * 1024ull];

static constexpr int NST      = 3;
static constexpr int STAGE    = 32768;              // A 16KB + B 16KB
static constexpr int MBAR_OFF = NST * STAGE;        // 98304
static constexpr int SMEM     = MBAR_OFF + 64;      // 98368

__device__ __forceinline__ uint32_t s2u(const void* p) {
    uint32_t a;
    asm("{ .reg .u64 t; cvta.to.shared.u64 t, %1; cvt.u32.u64 %0, t; }"
        : "=r"(a) : "l"(p));
    return a;
}
__device__ __forceinline__ void mbar_init(uint32_t mb, uint32_t cnt) {
    asm volatile("mbarrier.init.shared.b64 [%0], %1;" :: "r"(mb), "r"(cnt)
                 : "memory");
}
__device__ __forceinline__ void mbar_arrive(uint32_t mb) {
    asm volatile("mbarrier.arrive.shared.b64 _, [%0];" :: "r"(mb) : "memory");
}
__device__ __forceinline__ void cp_arrive_noinc(uint32_t mb) {
    asm volatile("cp.async.mbarrier.arrive.noinc.shared.b64 [%0];" :: "r"(mb)
                 : "memory");
}
__device__ __forceinline__ void mbar_wait(uint32_t mb, uint32_t parity) {
    asm volatile(
        "{\n\t.reg .pred P;\n\t"
        "WL_%=:\n\t"
        "mbarrier.try_wait.parity.acquire.cta.shared::cta.b64 P, [%0], %1, 0x989680;\n\t"
        "@P bra WD_%=;\n\t"
        "bra WL_%=;\n\t"
        "WD_%=:\n\t}"
        :: "r"(mb), "r"(parity) : "memory");
}
__device__ __forceinline__ void ldsm4(uint32_t& r0, uint32_t& r1,
                                      uint32_t& r2, uint32_t& r3, uint32_t a) {
    asm volatile("ldmatrix.sync.aligned.m8n8.x4.shared.b16 {%0,%1,%2,%3}, [%4];"
                 : "=r"(r0), "=r"(r1), "=r"(r2), "=r"(r3) : "r"(a));
}
__device__ __forceinline__ void mma_f16(float* d, const uint32_t* a,
                                        uint32_t b0, uint32_t b1) {
    asm volatile(
        "mma.sync.aligned.m16n8k16.row.col.f32.f16.f16.f32 "
        "{%0,%1,%2,%3}, {%4,%5,%6,%7}, {%8,%9}, {%0,%1,%2,%3};\n"
        : "+f"(d[0]), "+f"(d[1]), "+f"(d[2]), "+f"(d[3])
        : "r"(a[0]), "r"(a[1]), "r"(a[2]), "r"(a[3]), "r"(b0), "r"(b1));
}
__device__ __forceinline__ float tanh_a(float x) {
    float y;
    asm("tanh.approx.f32 %0, %1;" : "=f"(y) : "f"(x));
    return y;
}
__device__ __forceinline__ float sigm_a(float x) {
    return fmaf(tanh_a(0.5f * x), 0.5f, 0.5f);
}

// ---- prepass: activations + weights -> f16 scratch -------------------------
__global__ __launch_bounds__(256)
void prep(const float* __restrict__ x, const float* __restrict__ h,
          const float* __restrict__ s, const float* __restrict__ t,
          const float* __restrict__ Wx, const float* __restrict__ Wh,
          const float* __restrict__ Ws, const float* __restrict__ Wt,
          int ablocks) {
    const int tid = threadIdx.x;
    if ((int)blockIdx.x < ablocks) {
        const int idx = blockIdx.x * 256 + tid;
        const int r   = idx >> 6;
        const int k16 = (idx & 63) * 16;
        const float* ap; int astr, kl;
        if (k16 < 256)      { ap = x; astr = 256; kl = k16;       }
        else if (k16 < 768) { ap = h; astr = 512; kl = k16 - 256; }
        else if (k16 < 896) { ap = s; astr = 128; kl = k16 - 768; }
        else                { ap = t; astr = 128; kl = k16 - 896; }
        const float4* src = reinterpret_cast<const float4*>(
            ap + (size_t)r * astr + kl);
        const float4 f0 = src[0], f1 = src[1], f2 = src[2], f3 = src[3];
        __half2 h0 = __floats2half2_rn(f0.x, f0.y);
        __half2 h1 = __floats2half2_rn(f0.z, f0.w);
        __half2 h2 = __floats2half2_rn(f1.x, f1.y);
        __half2 h3 = __floats2half2_rn(f1.z, f1.w);
        __half2 h4 = __floats2half2_rn(f2.x, f2.y);
        __half2 h5 = __floats2half2_rn(f2.z, f2.w);
        __half2 h6 = __floats2half2_rn(f3.x, f3.y);
        __half2 h7 = __floats2half2_rn(f3.z, f3.w);
        uint4* dst = reinterpret_cast<uint4*>(g_Af16 + (size_t)r * 1024 + k16);
        dst[0] = make_uint4(*(uint32_t*)&h0, *(uint32_t*)&h1,
                            *(uint32_t*)&h2, *(uint32_t*)&h3);
        dst[1] = make_uint4(*(uint32_t*)&h4, *(uint32_t*)&h5,
                            *(uint32_t*)&h6, *(uint32_t*)&h7);
    } else {
        __shared__ float tile[32][33];
        const int wb = blockIdx.x - ablocks;      // 0..2047
        const int k0 = (wb & 31) * 32;
        const int r0 = (wb >> 5) * 32;
        const float* wp; int kl;
        if (k0 < 256)      { wp = Wx; kl = k0;       }
        else if (k0 < 768) { wp = Wh; kl = k0 - 256; }
        else if (k0 < 896) { wp = Ws; kl = k0 - 768; }
        else               { wp = Wt; kl = k0 - 896; }
        const int tx = tid & 31, ty = tid >> 5;
        const int r = r0 + tx;
        const int c = ((r >> 3) & 3) * 512 + (r >> 7) * 32 +
                      ((r >> 5) & 3) * 8 + (r & 7);
#pragma unroll
        for (int i = 0; i < 4; i++) {
            const int ky = ty + 8 * i;
            tile[tx][ky] = wp[(size_t)(kl + ky) * 2048 + c];
        }
        __syncthreads();
#pragma unroll
        for (int i = 0; i < 4; i++) {
            const int ky = ty + 8 * i;
            g_Wf16[(size_t)(r0 + ky) * 1024 + k0 + tx] =
                __half_as_ushort(__float2half_rn(tile[ky][tx]));
        }
    }
}

// ---- main GEMM + gates ------------------------------------------------------
__global__ __launch_bounds__(256, 2)
void lstm_gemm(const float* __restrict__ cin, const float* __restrict__ bh,
               float* __restrict__ out, int B)
{
    extern __shared__ __align__(1024) char smem[];
    const uint32_t sb = s2u(smem);
    const uint32_t mb_full  = sb + MBAR_OFF;        // 3 x 8B, count 256
    const uint32_t mb_empty = sb + MBAR_OFF + 24;   // 3 x 8B, count 8 (warps)
    const int tid  = threadIdx.x;
    const int wid  = tid >> 5;
    const int lane = tid & 31;
    const int gid  = lane >> 2;
    const int tig  = lane & 3;
    const int wm   = wid & 1;       // M half  (64 rows)
    const int wn   = wid >> 1;      // N quarter (32 preact cols)
    const int m0   = blockIdx.x * 128;
    const int by   = blockIdx.y;    // 32-hidden-col block
    // chunk-order rotation: decorrelate k-chunk addresses across CTAs
    const int off  = (blockIdx.x * 3 + blockIdx.y) & 15;

    float acc[4][4][4];
#pragma unroll
    for (int mt = 0; mt < 4; mt++)
#pragma unroll
        for (int nt = 0; nt < 4; nt++)
#pragma unroll
            for (int q = 0; q < 4; q++) acc[mt][nt][q] = 0.0f;

    const uint16_t* Abase = g_Af16 + (size_t)m0 * 1024;
    const uint16_t* Wbase = g_Wf16 + (size_t)by * 128 * 1024;

    // issue logical chunk q into stage stq (physical k-chunk rotated by off)
    auto issue = [&](int q, int stq) {
        const uint32_t base = sb + stq * STAGE;
        const int kg = ((q + off) & 15) * 64;
#pragma unroll
        for (int i = 0; i < 8; i++) {
            const int v   = tid + i * 256;
            const int mat = v >> 10;
            const int row = (v >> 3) & 127;
            const int seg = v & 7;
            const uint32_t dst = base + mat * 16384 + row * 128 +
                                 (seg ^ (row & 7)) * 16;
            const uint16_t* src = (mat ? Wbase : Abase) +
                                  (size_t)row * 1024 + kg + seg * 8;
            asm volatile("cp.async.cg.shared.global [%0], [%1], 16;"
                         :: "r"(dst), "l"(src));
        }
        cp_arrive_noinc(mb_full + 8 * stq);
    };

    // one k16 step of the chunk in stage st
    auto compute_ks = [&](int st, int ks) {
        const uint32_t ab = sb + st * STAGE;
        const uint32_t bb = ab + 16384;
        uint32_t a[4][4];
#pragma unroll
        for (int mt = 0; mt < 4; mt++) {
            const int row = wm * 64 + mt * 16 + (lane & 7) +
                            8 * ((lane >> 3) & 1);
            const int seg = 2 * ks + ((lane >> 4) & 1);
            const uint32_t addr = ab + row * 128 + (seg ^ (row & 7)) * 16;
            ldsm4(a[mt][0], a[mt][1], a[mt][2], a[mt][3], addr);
        }
        uint32_t b[4][2];
#pragma unroll
        for (int np = 0; np < 2; np++) {
            const int row = wn * 32 + np * 16 + (lane & 7) +
                            8 * ((lane >> 4) & 1);
            const int seg = 2 * ks + ((lane >> 3) & 1);
            const uint32_t addr = bb + row * 128 + (seg ^ (row & 7)) * 16;
            ldsm4(b[2 * np][0], b[2 * np][1],
                  b[2 * np + 1][0], b[2 * np + 1][1], addr);
        }
#pragma unroll
        for (int mt = 0; mt < 4; mt++)
#pragma unroll
            for (int nt = 0; nt < 4; nt++)
                mma_f16(acc[mt][nt], a[mt], b[nt][0], b[nt][1]);
    };

    // prologue: mbarrier init; odd-bx CTAs delay ~half a chunk to interleave
    if (tid == 0) {
#pragma unroll
        for (int i = 0; i < NST; i++) {
            mbar_init(mb_full + 8 * i, 256);
            mbar_init(mb_empty + 8 * i, 8);
        }
    }
    __syncthreads();
    if (blockIdx.x & 1) __nanosleep(600);
    issue(0, 0);
    issue(1, 1);

    // mainloop: wait full -> ks0 -> (wait empty + issue, overlapped) -> ks1-3
#pragma unroll 1
    for (int s = 0; s < 16; s++) {
        const int d  = (s * 11) >> 5;        // s / 3 for s < 18
        const int st = s - 3 * d;
        mbar_wait(mb_full + 8 * st, d & 1);
        compute_ks(st, 0);
        const int q = s + 2;
        if (q < 16) {
            const int dq  = (q * 11) >> 5;
            const int stq = q - 3 * dq;
            if (q >= NST)
                mbar_wait(mb_empty + 8 * stq, (dq - 1) & 1);
            issue(q, stq);
        }
        compute_ks(st, 1);
        compute_ks(st, 2);
        compute_ks(st, 3);
        if (lane == 0)
            mbar_arrive(mb_empty + 8 * st);
    }

    // epilogue: register-local gates, per-warp retirement
    const int jl0 = wn * 8 + 2 * tig;         // hidden col within 32-block
    const int jg  = by * 32 + jl0;
    float bv[4][2];
#pragma unroll
    for (int g = 0; g < 4; g++) {
        bv[g][0] = __ldg(&bh[g * 512 + jg]);
        bv[g][1] = __ldg(&bh[g * 512 + jg + 1]);
    }
    const int rowbase = m0 + wm * 64 + gid;
#pragma unroll
    for (int mt = 0; mt < 4; mt++) {
#pragma unroll
        for (int rh = 0; rh < 2; rh++) {
            const int row = rowbase + mt * 16 + 8 * rh;
            const float2 cv = *reinterpret_cast<const float2*>(
                cin + (size_t)row * 512 + jg);
            float hn[2], cn[2];
#pragma unroll
            for (int e = 0; e < 2; e++) {
                const int ci = rh * 2 + e;
                const float pi = acc[mt][0][ci] + bv[0][e];
                const float pf = acc[mt][1][ci] + bv[1][e];
                const float po = acc[mt][2][ci] + bv[2][e];
                const float pc = acc[mt][3][ci] + bv[3][e];
                const float ig = sigm_a(pi);
                const float fg = sigm_a(pf);
                const float og = sigm_a(po);
                const float cg = tanh_a(pc);
                const float c_ = (e ? cv.y : cv.x);
                cn[e] = fg * c_ + ig * cg;
                hn[e] = tanh_a(og * cn[e]);
            }
            *reinterpret_cast<float2*>(out + (size_t)row * 512 + jg) =
                make_float2(hn[0], hn[1]);
            *reinterpret_cast<float2*>(out + (size_t)B * 512 +
                                       (size_t)row * 512 + jg) =
                make_float2(cn[0], cn[1]);
        }
    }
}

extern "C" void kernel_launch(void* const* d_in, const int* in_sizes, int n_in,
                              void* d_out, int out_size) {
    const float* x  = (const float*)d_in[0];
    const float* h  = (const float*)d_in[1];
    const float* c  = (const float*)d_in[2];
    const float* sp = (const float*)d_in[3];
    const float* tp = (const float*)d_in[4];
    const float* Wx = (const float*)d_in[5];
    const float* Wh = (const float*)d_in[6];
    const float* bh = (const float*)d_in[7];
    const float* Ws = (const float*)d_in[8];
    const float* Wt = (const float*)d_in[9];
    float* out = (float*)d_out;

    const int B = in_sizes[0] / 256;   // x is [B, 256]
    const int ablocks = (B * 1024) / (256 * 16);

    static int smem_set = 0;
    if (!smem_set) {
        cudaFuncSetAttribute(lstm_gemm,
                             cudaFuncAttributeMaxDynamicSharedMemorySize, SMEM);
        smem_set = 1;
    }

    prep<<<ablocks + 2048, 256>>>(x, h, sp, tp, Wx, Wh, Ws, Wt, ablocks);
    lstm_gemm<<<dim3(B / 128, 16), 256, SMEM>>>(c, bh, out, B);
}